// round 6
// baseline (speedup 1.0000x reference)
#include <cuda_runtime.h>
#include <math.h>

#define B_   4
#define LQ   1024
#define LK   2048
#define H_   8
#define HID  256
#define D_   32
#define TEMP_INV 10.0f
#define LOG2E 1.4426950408889634f
#define KP   20    // padded per-row float count (16 k-slots + kc-slot unused + pad), bank-conflict-free stride

// ---------------- scratch (device globals; no allocations) ----------------
__device__ float g_G[H_ * 12 * 12];                   // per-head bilinear form (LOG2E-scaled)
__device__ float g_R[88 * HID];                       // fused Av_h @ Wo_h^T
__device__ float g_obias[HID];                        // bo + bv @ Wo^T
__device__ float g_Qt[(size_t)B_ * H_ * LQ * KP];     // Q-hat, row-major [bh][q][k0..15 (tf32-rounded), 16..19=0]
__device__ float g_Kt[(size_t)B_ * LK * KP];          // raw key feats [b][k][j0..10, 11..19=0]
__device__ float g_kc[(size_t)B_ * H_ * LK];          // -beta*kn*LOG2E per head (fp32)
__device__ float g_cr[(size_t)B_ * LQ * 88];          // ctxRaw

__device__ __forceinline__ float sigmoidf_(float x) { return 1.f / (1.f + expf(-x)); }

__device__ __forceinline__ float ex2f(float x) {
    float r;
    asm("ex2.approx.ftz.f32 %0, %1;" : "=f"(r) : "f"(x));
    return r;
}
__device__ __forceinline__ float tf32r(float x) {
    unsigned u;
    asm("cvt.rna.tf32.f32 %0, %1;" : "=r"(u) : "f"(x));
    return __uint_as_float(u);
}
// D += A(16x8) * B(8x8), tf32 inputs (fp32 regs, HW-truncated on B side; A pre-rounded)
__device__ __forceinline__ void mma_tf32(float c[4],
                                         float a0, float a1, float a2, float a3,
                                         float b0, float b1) {
    asm volatile(
        "mma.sync.aligned.m16n8k8.row.col.f32.tf32.tf32.f32 "
        "{%0,%1,%2,%3}, {%4,%5,%6,%7}, {%8,%9}, {%0,%1,%2,%3};"
        : "+f"(c[0]), "+f"(c[1]), "+f"(c[2]), "+f"(c[3])
        : "r"(__float_as_uint(a0)), "r"(__float_as_uint(a1)),
          "r"(__float_as_uint(a2)), "r"(__float_as_uint(a3)),
          "r"(__float_as_uint(b0)), "r"(__float_as_uint(b1)));
}

// ---------------- P0: fold weights into G_h, R, obias ----------------
__global__ void p0_params(const float* __restrict__ Wq_s, const float* __restrict__ bq_s,
                          const float* __restrict__ Wk_s, const float* __restrict__ bk_s,
                          const float* __restrict__ Wq_w, const float* __restrict__ bq_w,
                          const float* __restrict__ Wk_w, const float* __restrict__ bk_w,
                          const float* __restrict__ Wv,   const float* __restrict__ bv,
                          const float* __restrict__ Wo,   const float* __restrict__ bo,
                          const float* __restrict__ wb)
{
    int t = threadIdx.x;
    int blk = blockIdx.x;
    if (blk == H_) {
        float acc = bo[t];
        for (int u = 0; u < HID; u++) acc += bv[u] * Wo[t * HID + u];
        g_obias[t] = acc;
        return;
    }
    int h = blk;
    float alpha = sigmoidf_(wb[0]);
    float c1 = (1.f - alpha) / sqrtf((float)D_) * LOG2E;
    float c2 = 2.f * alpha * TEMP_INV * LOG2E;

    if (t < 144) {
        int r = t / 12, c = t % 12;
        float acc = 0.f;
        if (r < 8 && c < 8) {
            for (int d = 0; d < 32; d++) acc += Wq_s[(h*32+d)*8 + r] * Wk_s[(h*32+d)*8 + c];
            acc *= c1;
        } else if (r < 8 && c == 11) {
            for (int d = 0; d < 32; d++) acc += Wq_s[(h*32+d)*8 + r] * bk_s[h*32+d];
            acc *= c1;
        } else if (r >= 8 && r < 11 && c >= 8 && c < 11) {
            for (int d = 0; d < 32; d++) acc += Wq_w[(h*32+d)*3 + (r-8)] * Wk_w[(h*32+d)*3 + (c-8)];
            acc *= c2;
        } else if (r >= 8 && r < 11 && c == 11) {
            for (int d = 0; d < 32; d++) acc += Wq_w[(h*32+d)*3 + (r-8)] * bk_w[h*32+d];
            acc *= c2;
        } else if (r == 11 && c < 8) {
            for (int d = 0; d < 32; d++) acc += bq_s[h*32+d] * Wk_s[(h*32+d)*8 + c];
            acc *= c1;
        } else if (r == 11 && c >= 8 && c < 11) {
            for (int d = 0; d < 32; d++) acc += bq_w[h*32+d] * Wk_w[(h*32+d)*3 + (c-8)];
            acc *= c2;
        } else if (r == 11 && c == 11) {
            float a1 = 0.f, a2 = 0.f;
            for (int d = 0; d < 32; d++) {
                a1 += bq_s[h*32+d] * bk_s[h*32+d];
                a2 += bq_w[h*32+d] * bk_w[h*32+d];
            }
            acc = c1 * a1 + c2 * a2;
        }
        g_G[(h*12 + r)*12 + c] = acc;
    }
    float wo[32];
    #pragma unroll
    for (int d = 0; d < 32; d++) wo[d] = Wo[t * HID + h*32 + d];
    for (int j = 0; j < 11; j++) {
        float acc = 0.f;
        #pragma unroll
        for (int d = 0; d < 32; d++) acc += Wv[(h*32+d)*11 + j] * wo[d];
        g_R[(h*11 + j) * HID + t] = acc;
    }
}

// ---------------- P1q: Q-hat row-major, tf32-rounded, zero-padded to 16 k-slots ----------------
__global__ void __launch_bounds__(128)
p1_q(const float* __restrict__ q_fp)
{
    __shared__ float Gs[H_ * 144];
    int t = threadIdx.x;
    for (int i = t; i < H_ * 144; i += 128) Gs[i] = g_G[i];
    __syncthreads();

    int idx = blockIdx.x * 128 + t;   // b*LQ + q
    int b = idx >> 10, q = idx & (LQ - 1);

    float x[11];
    #pragma unroll
    for (int j = 0; j < 11; j++) x[j] = q_fp[(size_t)idx * 11 + j];

    for (int h = 0; h < H_; h++) {
        size_t base = ((size_t)(b * H_ + h) * LQ + q) * KP;
        const float* Gh = &Gs[h * 144];
        #pragma unroll
        for (int c = 0; c < 11; c++) {
            float a = Gh[11*12 + c];
            #pragma unroll
            for (int r = 0; r < 11; r++) a += x[r] * Gh[r*12 + c];
            g_Qt[base + c] = tf32r(a);
        }
        #pragma unroll
        for (int c = 11; c < KP; c++) g_Qt[base + c] = 0.f;
    }
}

// ---------------- P1k: raw K features key-major + per-head kn term ----------------
__global__ void __launch_bounds__(128)
p1_k(const float* __restrict__ v_ret, const float* __restrict__ Wk_w,
     const float* __restrict__ bk_w, const float* __restrict__ wb)
{
    __shared__ float Ws[HID * 3];
    __shared__ float Bs[HID];
    int t = threadIdx.x;
    for (int i = t; i < HID * 3; i += 128) Ws[i] = Wk_w[i];
    for (int i = t; i < HID;     i += 128) Bs[i] = bk_w[i];
    __syncthreads();

    float alpha = sigmoidf_(wb[0]);
    float beta2 = alpha * TEMP_INV * LOG2E;
    int idx = blockIdx.x * 128 + t;   // b*LK + k

    float x[11];
    #pragma unroll
    for (int j = 0; j < 11; j++) x[j] = v_ret[(size_t)idx * 11 + j];

    size_t kb = (size_t)idx * KP;
    #pragma unroll
    for (int j = 0; j < 11; j++) g_Kt[kb + j] = x[j];
    #pragma unroll
    for (int j = 11; j < KP; j++) g_Kt[kb + j] = 0.f;

    int b = idx >> 11, k = idx & (LK - 1);
    for (int h = 0; h < H_; h++) {
        float kn = 0.f;
        #pragma unroll 4
        for (int d = 0; d < 32; d++) {
            float s = Bs[h*32 + d];
            s += x[8]  * Ws[(h*32+d)*3 + 0];
            s += x[9]  * Ws[(h*32+d)*3 + 1];
            s += x[10] * Ws[(h*32+d)*3 + 2];
            kn += s * s;
        }
        g_kc[(size_t)(b * H_ + h) * LK + k] = -beta2 * kn;
    }
}

// ---------------- main attention: tf32 mma QK + fp32 SIMT PV, no online max ----------------
// 256 threads = 8 warps. Warp w: row-block rb=w&3 (16 rows), key-half kh=w>>2 (32 keys).
__global__ void __launch_bounds__(256, 2)
attn_kernel(const float* __restrict__ pi)
{
    __shared__ __align__(16) float Qt[64 * KP];        // staged Q-hat tile
    __shared__ __align__(16) float Kt[2][64 * KP];     // staged K tiles (double buffer)
    __shared__ __align__(16) float kcS[2][64];
    __shared__ float Os[64][11];
    __shared__ float ls[64];

    int t = threadIdx.x;
    int lane = t & 31, w = t >> 5;
    int m = lane & 3, r = lane >> 2;
    int rb = w & 3, kh = w >> 2;
    int h = blockIdx.x, qt_ = blockIdx.y, b = blockIdx.z;
    int bh = b * H_ + h;
    int q0 = qt_ * 64;

    // stage Qt (once per CTA) and first K tile + kc
    {
        const float4* qsrc = (const float4*)&g_Qt[((size_t)bh * LQ + q0) * KP];
        const float4* ksrc = (const float4*)&g_Kt[((size_t)b * LK) * KP];
        float4* qd = (float4*)Qt;
        float4* kd = (float4*)Kt[0];
        for (int i = t; i < 320; i += 256) { qd[i] = qsrc[i]; kd[i] = ksrc[i]; }
        if (t < 16)
            ((float4*)kcS[0])[t] = ((const float4*)&g_kc[(size_t)bh * LK])[t];
    }
    __syncthreads();

    // A fragments (Q side): loop-invariant, load once. Rows rb*16 + {r, r+8}.
    float aF[2][4];
    #pragma unroll
    for (int ks = 0; ks < 2; ks++) {
        int kof = ks * 8 + m;
        aF[ks][0] = Qt[(rb*16 + r    ) * KP + kof];
        aF[ks][1] = Qt[(rb*16 + r + 8) * KP + kof];
        aF[ks][2] = Qt[(rb*16 + r    ) * KP + kof + 4];
        aF[ks][3] = Qt[(rb*16 + r + 8) * KP + kof + 4];
    }

    float O[2][11];
    float l0 = 0.f, l1 = 0.f;
    #pragma unroll
    for (int c = 0; c < 11; c++) { O[0][c] = 0.f; O[1][c] = 0.f; }

    // pi row pointers (fp32, log2 computed in-loop; L2-resident across heads)
    const float* piR0 = pi + ((size_t)(b * LQ + q0 + rb*16 + r)) * LK + kh*32 + 2*m;
    const float* piR1 = piR0 + (size_t)8 * LK;

    // software-pipelined pi loads
    float2 lpc[2][4], lpn[2][4];
    #pragma unroll
    for (int s = 0; s < 4; s++) {
        lpc[0][s] = *(const float2*)(piR0 + s*8);
        lpc[1][s] = *(const float2*)(piR1 + s*8);
    }

    for (int kt = 0; kt < 32; kt++) {
        int cur = kt & 1;
        int k0 = kt * 64;

        // prefetch next pi tile + stage next K tile
        if (kt < 31) {
            #pragma unroll
            for (int s = 0; s < 4; s++) {
                lpn[0][s] = *(const float2*)(piR0 + k0 + 64 + s*8);
                lpn[1][s] = *(const float2*)(piR1 + k0 + 64 + s*8);
            }
            const float4* ksrc = (const float4*)&g_Kt[((size_t)b * LK + k0 + 64) * KP];
            float4* kd = (float4*)Kt[cur ^ 1];
            for (int i = t; i < 320; i += 256) kd[i] = ksrc[i];
            if (t < 16)
                ((float4*)kcS[cur ^ 1])[t] =
                    ((const float4*)&g_kc[(size_t)bh * LK + k0 + 64])[t];
        }

        // ---- QK via tf32 mma: S(16x32 per warp) = Qhat(16x16) . K^T ----
        float S[4][4];
        #pragma unroll
        for (int s = 0; s < 4; s++) {
            S[s][0] = 0.f; S[s][1] = 0.f; S[s][2] = 0.f; S[s][3] = 0.f;
            int n0 = kh*32 + s*8;
            #pragma unroll
            for (int ks = 0; ks < 2; ks++) {
                float b0 = Kt[cur][(n0 + r) * KP + ks*8 + m];
                float b1 = Kt[cur][(n0 + r) * KP + ks*8 + m + 4];
                mma_tf32(S[s], aF[ks][0], aF[ks][1], aF[ks][2], aF[ks][3], b0, b1);
            }
        }

        // ---- + kc + log2(pi), exp2 ----
        #pragma unroll
        for (int s = 0; s < 4; s++) {
            float2 kcp = *(const float2*)&kcS[cur][kh*32 + s*8 + 2*m];
            S[s][0] = ex2f(S[s][0] + kcp.x + __log2f(fmaxf(lpc[0][s].x, 1e-9f)));
            S[s][1] = ex2f(S[s][1] + kcp.y + __log2f(fmaxf(lpc[0][s].y, 1e-9f)));
            S[s][2] = ex2f(S[s][2] + kcp.x + __log2f(fmaxf(lpc[1][s].x, 1e-9f)));
            S[s][3] = ex2f(S[s][3] + kcp.y + __log2f(fmaxf(lpc[1][s].y, 1e-9f)));
            l0 += S[s][0] + S[s][1];
            l1 += S[s][2] + S[s][3];
        }

        // ---- PV (fp32 SIMT): thread's 8 keys = pairs {kh*32+s*8+2m, +1} ----
        #pragma unroll
        for (int s = 0; s < 4; s++) {
            int key = kh*32 + s*8 + 2*m;
            const float* v0p = &Kt[cur][key * KP];
            const float* v1p = &Kt[cur][(key + 1) * KP];
            float4 a0 = *(const float4*)(v0p);
            float4 a1 = *(const float4*)(v0p + 4);
            float4 a2 = *(const float4*)(v0p + 8);
            float4 b0v = *(const float4*)(v1p);
            float4 b1v = *(const float4*)(v1p + 4);
            float4 b2v = *(const float4*)(v1p + 8);
            float va[11] = {a0.x,a0.y,a0.z,a0.w, a1.x,a1.y,a1.z,a1.w, a2.x,a2.y,a2.z};
            float vb[11] = {b0v.x,b0v.y,b0v.z,b0v.w, b1v.x,b1v.y,b1v.z,b1v.w, b2v.x,b2v.y,b2v.z};
            float p00 = S[s][0], p01 = S[s][1], p10 = S[s][2], p11 = S[s][3];
            #pragma unroll
            for (int c = 0; c < 11; c++) {
                O[0][c] += p00 * va[c] + p01 * vb[c];
                O[1][c] += p10 * va[c] + p11 * vb[c];
            }
        }

        // rotate pipelined lp
        #pragma unroll
        for (int s = 0; s < 4; s++) { lpc[0][s] = lpn[0][s]; lpc[1][s] = lpn[1][s]; }

        __syncthreads();
    }

    // ---- reduce over the 4 m-lanes (keys within half), then across key-halves via smem ----
    l0 += __shfl_xor_sync(0xffffffffu, l0, 1);
    l0 += __shfl_xor_sync(0xffffffffu, l0, 2);
    l1 += __shfl_xor_sync(0xffffffffu, l1, 1);
    l1 += __shfl_xor_sync(0xffffffffu, l1, 2);
    #pragma unroll
    for (int c = 0; c < 11; c++) {
        O[0][c] += __shfl_xor_sync(0xffffffffu, O[0][c], 1);
        O[0][c] += __shfl_xor_sync(0xffffffffu, O[0][c], 2);
        O[1][c] += __shfl_xor_sync(0xffffffffu, O[1][c], 1);
        O[1][c] += __shfl_xor_sync(0xffffffffu, O[1][c], 2);
    }

    int row = rb*16 + r;
    if (m == 0 && kh == 0) {
        #pragma unroll
        for (int c = 0; c < 11; c++) { Os[row][c] = O[0][c]; Os[row + 8][c] = O[1][c]; }
        ls[row] = l0; ls[row + 8] = l1;
    }
    __syncthreads();
    if (m == 0 && kh == 1) {
        float inv0 = 1.0f / (ls[row] + l0);
        float inv1 = 1.0f / (ls[row + 8] + l1);
        size_t base0 = ((size_t)(b * LQ + q0 + row)) * 88 + h * 11;
        size_t base1 = base0 + (size_t)8 * 88;
        #pragma unroll
        for (int c = 0; c < 11; c++) {
            g_cr[base0 + c] = (Os[row][c] + O[0][c]) * inv0;
            g_cr[base1 + c] = (Os[row + 8][c] + O[1][c]) * inv1;
        }
    }
}

// ---------------- epilogue: out = ctxRaw(4096x88) @ R(88x256) + obias ----------------
__global__ void __launch_bounds__(256)
epilogue_kernel(float* __restrict__ out)
{
    __shared__ float crsT[88][32];
    int t = threadIdx.x;
    int row0 = blockIdx.x * 32;

    for (int i = t; i < 32 * 88; i += 256) {
        int r = i / 88, j = i % 88;
        crsT[j][r] = g_cr[(size_t)(row0 + r) * 88 + j];
    }
    __syncthreads();

    float acc[32];
    #pragma unroll
    for (int r = 0; r < 32; r++) acc[r] = 0.f;

    #pragma unroll 4
    for (int j = 0; j < 88; j++) {
        float rv = g_R[j * HID + t];
        #pragma unroll
        for (int r = 0; r < 32; r += 4) {
            float4 cv = *(const float4*)&crsT[j][r];
            acc[r]     += cv.x * rv;
            acc[r + 1] += cv.y * rv;
            acc[r + 2] += cv.z * rv;
            acc[r + 3] += cv.w * rv;
        }
    }

    float ob = g_obias[t];
    for (int r = 0; r < 32; r++)
        out[(size_t)(row0 + r) * HID + t] = acc[r] + ob;
}

// ---------------- launch ----------------
extern "C" void kernel_launch(void* const* d_in, const int* in_sizes, int n_in,
                              void* d_out, int out_size)
{
    const float* q_fp  = (const float*)d_in[0];
    const float* v_ret = (const float*)d_in[1];
    const float* pi    = (const float*)d_in[2];
    const float* Wq_s  = (const float*)d_in[3];
    const float* bq_s  = (const float*)d_in[4];
    const float* Wk_s  = (const float*)d_in[5];
    const float* bk_s  = (const float*)d_in[6];
    const float* Wq_w  = (const float*)d_in[7];
    const float* bq_w  = (const float*)d_in[8];
    const float* Wk_w  = (const float*)d_in[9];
    const float* bk_w  = (const float*)d_in[10];
    const float* Wv    = (const float*)d_in[11];
    const float* bv    = (const float*)d_in[12];
    const float* Wo    = (const float*)d_in[13];
    const float* bo    = (const float*)d_in[14];
    const float* wb    = (const float*)d_in[15];
    float* out = (float*)d_out;

    p0_params<<<H_ + 1, 256>>>(Wq_s, bq_s, Wk_s, bk_s, Wq_w, bq_w, Wk_w, bk_w,
                               Wv, bv, Wo, bo, wb);
    p1_q<<<(B_ * LQ) / 128, 128>>>(q_fp);
    p1_k<<<(B_ * LK) / 128, 128>>>(v_ret, Wk_w, bk_w, wb);
    dim3 g(H_, LQ / 64, B_);
    attn_kernel<<<g, 256>>>(pi);
    epilogue_kernel<<<(B_ * LQ) / 32, 256>>>(out);
}